// round 6
// baseline (speedup 1.0000x reference)
#include <cuda_runtime.h>
#include <cuda_bf16.h>

// VectorQuantizer: latents [32,64,64,64] (B,D,H,W), emb [512,64].
// out[0..N*D) = straight-through quantized tensor (B,D,H,W); out[last] = vq_loss.
//
// R4: bf16 tensor-core (mma.sync m16n8k16) coarse scoring + margin-based
// candidate collection + exact fp32 re-rank (bit-identical to reference chain).

#define VQ_K     512
#define VQ_D     64
#define VQ_HW    4096
#define VQ_NPIX  131072
#define VQ_ND    8388608
#define THREADS  256
#define PPB      256                      // pixels per block
#define NBLOCKS  (VQ_NPIX / PPB)          // 512
#define MARGIN   4e-3f
#define CAND_MAX 8

// smem layout (byte offsets), total 210944 B
#define OFF_EMB    0                       // float [512][65]  = 133120
#define OFF_BPACK  133120                  // u64   [64*4*32]  =  65536
#define OFF_S      198656                  // float [512]      =   2048
#define OFF_PMIN   200704                  // float [256]      =   1024
#define OFF_CNT    201728                  // int   [256]      =   1024
#define OFF_CAND   202752                  // int   [256*8]    =   8192
#define SMEM_BYTES 210944

__device__ double g_loss_acc;              // zero-initialized; finalize re-zeros

#define CVTPACK(dst, hi, lo) \
    asm("cvt.rn.bf16x2.f32 %0, %1, %2;" : "=r"(dst) : "f"(hi), "f"(lo))

#define HMMA(acc, a, b0v, b1v) \
    asm volatile("mma.sync.aligned.m16n8k16.row.col.f32.bf16.bf16.f32 " \
                 "{%0,%1,%2,%3}, {%4,%5,%6,%7}, {%8,%9}, {%0,%1,%2,%3};" \
                 : "+f"(acc[0]), "+f"(acc[1]), "+f"(acc[2]), "+f"(acc[3]) \
                 : "r"(a[0]), "r"(a[1]), "r"(a[2]), "r"(a[3]), \
                   "r"(b0v), "r"(b1v))

__global__ void __launch_bounds__(THREADS)
vq_main_kernel(const float* __restrict__ lat,
               const float* __restrict__ emb,
               float* __restrict__ out) {
    extern __shared__ char smraw[];
    float*              sm_emb   = (float*)(smraw + OFF_EMB);     // [k*65 + d]
    unsigned long long* sm_bpack = (unsigned long long*)(smraw + OFF_BPACK);
    float*              sm_s     = (float*)(smraw + OFF_S);
    float*              sm_pmin  = (float*)(smraw + OFF_PMIN);
    int*                sm_cnt   = (int*)(smraw + OFF_CNT);
    int*                sm_cand  = (int*)(smraw + OFF_CAND);

    const int tid  = threadIdx.x;
    const int lane = tid & 31;
    const int w    = tid >> 5;
    const int g    = lane >> 2;       // group id (0..7)
    const int tg   = lane & 3;        // thread-in-group (0..3)
    const int pw   = w * 32;          // warp's pixel base within block

    const int n0    = blockIdx.x * PPB;
    const int bidx  = n0 >> 12;       // batch (block never straddles: 4096 % 256 == 0)
    const int sbase = n0 & 4095;
    const float* latb = lat + (size_t)bidx * (VQ_D * VQ_HW) + sbase;
    float*       outb = out + (size_t)bidx * (VQ_D * VQ_HW) + sbase;

    // ---- stage fp32 codebook (padded rows) + zero candidate counts
    for (int i = tid; i < VQ_K * VQ_D / 4; i += THREADS) {
        float4 v = ((const float4*)emb)[i];
        int k = i >> 4, dg = (i & 15) * 4;
        float* dst = sm_emb + k * 65 + dg;
        dst[0] = v.x; dst[1] = v.y; dst[2] = v.z; dst[3] = v.w;
    }
    sm_cnt[tid] = 0;
    __syncthreads();

    // ---- exact ||e||^2 chains (conflict-free: lane k, bank (k+d)%32)
    for (int k = tid; k < VQ_K; k += THREADS) {
        float acc = 0.0f;
#pragma unroll
        for (int d = 0; d < VQ_D; d++) {
            float v = sm_emb[k * 65 + d];
            acc = __fadd_rn(acc, __fmul_rn(v, v));
        }
        sm_s[k] = acc;
    }
    // ---- pre-packed bf16 B fragments: [nt][ks][lane] -> {b0,b1}
    for (int i = tid; i < 64 * 4 * 32; i += THREADS) {
        int nt = i >> 7, ks = (i >> 5) & 3, ln = i & 31;
        int gg = ln >> 2, tt = ln & 3;
        const float* er = sm_emb + (nt * 8 + gg) * 65 + ks * 16 + tt * 2;
        unsigned b0, b1;
        CVTPACK(b0, er[1], er[0]);
        CVTPACK(b1, er[9], er[8]);
        sm_bpack[i] = ((unsigned long long)b1 << 32) | b0;
    }
    __syncthreads();

    // ---- A fragments (2 m-tiles x 4 k-steps x 4 regs), bf16 from gmem fp32
    unsigned afr[2][4][4];
#pragma unroll
    for (int mt = 0; mt < 2; mt++)
#pragma unroll
        for (int ks = 0; ks < 4; ks++) {
            int p0 = pw + mt * 16 + g;
            int d0 = ks * 16 + tg * 2;
            const float* r0 = latb + (size_t)d0 * VQ_HW;
            CVTPACK(afr[mt][ks][0], r0[VQ_HW + p0],           r0[p0]);
            CVTPACK(afr[mt][ks][1], r0[VQ_HW + p0 + 8],       r0[p0 + 8]);
            CVTPACK(afr[mt][ks][2], r0[9 * VQ_HW + p0],       r0[8 * VQ_HW + p0]);
            CVTPACK(afr[mt][ks][3], r0[9 * VQ_HW + p0 + 8],   r0[8 * VQ_HW + p0 + 8]);
        }

    // ---- sweep 1: per-pixel coarse min of c_k = fma(-2, dot_bf16, s_k)
    float mn[4] = {3.4e38f, 3.4e38f, 3.4e38f, 3.4e38f};
#pragma unroll 1
    for (int nt = 0; nt < 64; nt++) {
        float a0[4] = {0, 0, 0, 0}, a1[4] = {0, 0, 0, 0};
#pragma unroll
        for (int ks = 0; ks < 4; ks++) {
            unsigned long long bv = sm_bpack[(nt * 4 + ks) * 32 + lane];
            unsigned b0 = (unsigned)bv, b1 = (unsigned)(bv >> 32);
            HMMA(a0, afr[0][ks], b0, b1);
            HMMA(a1, afr[1][ks], b0, b1);
        }
        float2 sp = *(const float2*)(sm_s + nt * 8 + tg * 2);
        float c00 = fmaf(-2.f, a0[0], sp.x), c01 = fmaf(-2.f, a0[1], sp.y);
        float c02 = fmaf(-2.f, a0[2], sp.x), c03 = fmaf(-2.f, a0[3], sp.y);
        float c10 = fmaf(-2.f, a1[0], sp.x), c11 = fmaf(-2.f, a1[1], sp.y);
        float c12 = fmaf(-2.f, a1[2], sp.x), c13 = fmaf(-2.f, a1[3], sp.y);
        mn[0] = fminf(mn[0], fminf(c00, c01));
        mn[1] = fminf(mn[1], fminf(c02, c03));
        mn[2] = fminf(mn[2], fminf(c10, c11));
        mn[3] = fminf(mn[3], fminf(c12, c13));
    }
#pragma unroll
    for (int j = 0; j < 4; j++) {
        mn[j] = fminf(mn[j], __shfl_xor_sync(~0u, mn[j], 1));
        mn[j] = fminf(mn[j], __shfl_xor_sync(~0u, mn[j], 2));
    }
    if (tg == 0) {
        sm_pmin[pw + g]      = mn[0];
        sm_pmin[pw + 8 + g]  = mn[1];
        sm_pmin[pw + 16 + g] = mn[2];
        sm_pmin[pw + 24 + g] = mn[3];
    }
    __syncwarp();

    // ---- sweep 2: identical dataflow -> bit-identical c; collect candidates
    const float lm0 = sm_pmin[pw + g] + MARGIN;
    const float lm1 = sm_pmin[pw + 8 + g] + MARGIN;
    const float lm2 = sm_pmin[pw + 16 + g] + MARGIN;
    const float lm3 = sm_pmin[pw + 24 + g] + MARGIN;
#define PUSH(p, kk) { int sl = atomicAdd(sm_cnt + (p), 1); \
                      if (sl < CAND_MAX) sm_cand[(p) * CAND_MAX + sl] = (kk); }
#pragma unroll 1
    for (int nt = 0; nt < 64; nt++) {
        float a0[4] = {0, 0, 0, 0}, a1[4] = {0, 0, 0, 0};
#pragma unroll
        for (int ks = 0; ks < 4; ks++) {
            unsigned long long bv = sm_bpack[(nt * 4 + ks) * 32 + lane];
            unsigned b0 = (unsigned)bv, b1 = (unsigned)(bv >> 32);
            HMMA(a0, afr[0][ks], b0, b1);
            HMMA(a1, afr[1][ks], b0, b1);
        }
        float2 sp = *(const float2*)(sm_s + nt * 8 + tg * 2);
        int kc = nt * 8 + tg * 2;
        float c;
        c = fmaf(-2.f, a0[0], sp.x); if (c <= lm0) PUSH(pw + g, kc);
        c = fmaf(-2.f, a0[1], sp.y); if (c <= lm0) PUSH(pw + g, kc + 1);
        c = fmaf(-2.f, a0[2], sp.x); if (c <= lm1) PUSH(pw + 8 + g, kc);
        c = fmaf(-2.f, a0[3], sp.y); if (c <= lm1) PUSH(pw + 8 + g, kc + 1);
        c = fmaf(-2.f, a1[0], sp.x); if (c <= lm2) PUSH(pw + 16 + g, kc);
        c = fmaf(-2.f, a1[1], sp.y); if (c <= lm2) PUSH(pw + 16 + g, kc + 1);
        c = fmaf(-2.f, a1[2], sp.x); if (c <= lm3) PUSH(pw + 24 + g, kc);
        c = fmaf(-2.f, a1[3], sp.y); if (c <= lm3) PUSH(pw + 24 + g, kc + 1);
    }
    __syncthreads();

    // ---- resolution: exact fp32 re-rank where ambiguous (reference chain)
    const int pl  = tid;
    const int cnt = sm_cnt[pl];
    int bi;
    if (cnt == 1) {
        bi = sm_cand[pl * CAND_MAX];
    } else {
        float x[VQ_D];
#pragma unroll
        for (int d = 0; d < VQ_D; d++)
            x[d] = latb[(size_t)d * VQ_HW + pl];
        float aa = 0.0f;
#pragma unroll
        for (int d = 0; d < VQ_D; d++)
            aa = __fadd_rn(aa, __fmul_rn(x[d], x[d]));
        float best = 3.4e38f;
        bi = 0;
        if (cnt <= CAND_MAX) {
            int cl[CAND_MAX];
            for (int i = 0; i < cnt; i++) cl[i] = sm_cand[pl * CAND_MAX + i];
            for (int i = 1; i < cnt; i++) {           // sort ascending k
                int v = cl[i], j = i;
                while (j > 0 && cl[j - 1] > v) { cl[j] = cl[j - 1]; j--; }
                cl[j] = v;
            }
            for (int i = 0; i < cnt; i++) {
                int k = cl[i];
                float dot = 0.0f;
#pragma unroll
                for (int d = 0; d < VQ_D; d++)
                    dot = __fmaf_rn(x[d], sm_emb[k * 65 + d], dot);
                float dist = __fmaf_rn(-2.0f, dot, __fadd_rn(aa, sm_s[k]));
                if (dist < best) { best = dist; bi = k; }
            }
        } else {                                      // overflow: full exact scan
            for (int k = 0; k < VQ_K; k++) {
                float dot = 0.0f;
#pragma unroll
                for (int d = 0; d < VQ_D; d++)
                    dot = __fmaf_rn(x[d], sm_emb[k * 65 + d], dot);
                float dist = __fmaf_rn(-2.0f, dot, __fadd_rn(aa, sm_s[k]));
                if (dist < best) { best = dist; bi = k; }
            }
        }
    }

    // ---- output + loss (bit-exact chains, double accumulation)
    const float* er = sm_emb + bi * 65;
    double lacc = 0.0;
#pragma unroll
    for (int d = 0; d < VQ_D; d++) {
        float xd = latb[(size_t)d * VQ_HW + pl];
        float dm = __fsub_rn(er[d], xd);
        outb[(size_t)d * VQ_HW + pl] = __fadd_rn(xd, dm);
        lacc += (double)__fmul_rn(dm, dm);
    }
#pragma unroll
    for (int off = 16; off > 0; off >>= 1)
        lacc += __shfl_down_sync(0xFFFFFFFFu, lacc, off);
    if ((tid & 31) == 0)
        atomicAdd(&g_loss_acc, lacc);
}

// vq_loss = fl( fl(m*0.25) + m ); then reset accumulator for next replay
__global__ void vq_finalize_kernel(float* __restrict__ out, int out_size) {
    double mean = g_loss_acc / (double)VQ_ND;
    float m = (float)mean;
    out[out_size - 1] = __fadd_rn(__fmul_rn(m, 0.25f), m);
    g_loss_acc = 0.0;
}

extern "C" void kernel_launch(void* const* d_in, const int* in_sizes, int n_in,
                              void* d_out, int out_size) {
    const float* lat = (const float*)d_in[0];
    const float* emb = (const float*)d_in[1];
    float* out = (float*)d_out;

    static bool attr_set = false;
    if (!attr_set) {
        cudaFuncSetAttribute(vq_main_kernel,
                             cudaFuncAttributeMaxDynamicSharedMemorySize,
                             SMEM_BYTES);
        attr_set = true;
    }

    vq_main_kernel<<<NBLOCKS, THREADS, SMEM_BYTES>>>(lat, emb, out);
    vq_finalize_kernel<<<1, 1>>>(out, out_size);
}